// round 4
// baseline (speedup 1.0000x reference)
#include <cuda_runtime.h>
#include <math.h>

#define BB 8
#define SS 1024
#define DD 1024
#define HH 16
#define HD 64
#define MTOT (BB*SS)   // 8192

// scratch for q, k, v in [B*S, D] layout (head h lives in columns h*64..h*64+63)
__device__ float g_q[(size_t)MTOT * DD];
__device__ float g_k[(size_t)MTOT * DD];
__device__ float g_v[(size_t)MTOT * DD];

// ---------------------------------------------------------------------------
// Kernel 1: QKV projection. out = x @ W + b for the three (W, b) pairs,
// selected by blockIdx.z. 64x64 tile, BK=16, 256 threads, 4x4 micro-tile.
// ---------------------------------------------------------------------------
__global__ void __launch_bounds__(256)
proj_kernel(const float* __restrict__ x,
            const float* __restrict__ Wq, const float* __restrict__ bq,
            const float* __restrict__ Wk, const float* __restrict__ bk,
            const float* __restrict__ Wv, const float* __restrict__ bv)
{
    const float* W; const float* bias; float* out;
    if (blockIdx.z == 0)      { W = Wq; bias = bq; out = g_q; }
    else if (blockIdx.z == 1) { W = Wk; bias = bk; out = g_k; }
    else                      { W = Wv; bias = bv; out = g_v; }

    __shared__ float As[16][65];   // [k][m], padded
    __shared__ float Bs[16][65];   // [k][n], padded

    const int tx = threadIdx.x % 16;
    const int ty = threadIdx.x / 16;
    const int mBase = blockIdx.y * 64;
    const int nBase = blockIdx.x * 64;

    float acc[4][4] = {};

    for (int k0 = 0; k0 < DD; k0 += 16) {
        // A tile: 64 rows x 16 k — one float4 per thread (64*16/4 = 256)
        {
            int i  = threadIdx.x;
            int m  = i / 4;
            int kq = (i % 4) * 4;
            float4 v4 = *(const float4*)(x + (size_t)(mBase + m) * DD + k0 + kq);
            As[kq + 0][m] = v4.x;
            As[kq + 1][m] = v4.y;
            As[kq + 2][m] = v4.z;
            As[kq + 3][m] = v4.w;
        }
        // B tile: 16 k x 64 n — one float4 per thread (16*64/4 = 256)
        {
            int i  = threadIdx.x;
            int kk = i / 16;
            int nq = (i % 16) * 4;
            float4 v4 = *(const float4*)(W + (size_t)(k0 + kk) * DD + nBase + nq);
            Bs[kk][nq + 0] = v4.x;
            Bs[kk][nq + 1] = v4.y;
            Bs[kk][nq + 2] = v4.z;
            Bs[kk][nq + 3] = v4.w;
        }
        __syncthreads();

        #pragma unroll
        for (int kk = 0; kk < 16; kk++) {
            float a[4], bvreg[4];
            #pragma unroll
            for (int i = 0; i < 4; i++) a[i] = As[kk][ty * 4 + i];
            #pragma unroll
            for (int j = 0; j < 4; j++) bvreg[j] = Bs[kk][tx * 4 + j];
            #pragma unroll
            for (int i = 0; i < 4; i++)
                #pragma unroll
                for (int j = 0; j < 4; j++)
                    acc[i][j] = fmaf(a[i], bvreg[j], acc[i][j]);
        }
        __syncthreads();
    }

    #pragma unroll
    for (int i = 0; i < 4; i++) {
        int m = mBase + ty * 4 + i;
        #pragma unroll
        for (int j = 0; j < 4; j++) {
            int n = nBase + tx * 4 + j;
            out[(size_t)m * DD + n] = acc[i][j] + bias[n];
        }
    }
}

// ---------------------------------------------------------------------------
// Kernel 2: per-(b,h) scores = Q @ K^T / 8, written (pre-softmax) into the
// attn_weights region of d_out. 64x64 tile over (q_row, k_row), K-dim = 64.
// ---------------------------------------------------------------------------
__global__ void __launch_bounds__(256)
scores_kernel(float* __restrict__ wout)
{
    const int bh = blockIdx.z;          // 0..127
    const int b = bh / HH, h = bh % HH;
    const int mBase = blockIdx.y * 64;
    const int nBase = blockIdx.x * 64;

    const float* qb = g_q + (size_t)b * SS * DD + h * HD;
    const float* kb = g_k + (size_t)b * SS * DD + h * HD;

    __shared__ float Qs[64][65];   // [row][d]
    __shared__ float Ks[64][65];   // [row][d]

    const int tx = threadIdx.x % 16;
    const int ty = threadIdx.x / 16;

    // 64x64 tiles, float4 loads: 64*64/4 = 1024 -> 4 iters per thread
    for (int i = threadIdx.x; i < 64 * 16; i += 256) {
        int r  = i / 16;
        int dq = (i % 16) * 4;
        float4 q4 = *(const float4*)(qb + (size_t)(mBase + r) * DD + dq);
        Qs[r][dq + 0] = q4.x; Qs[r][dq + 1] = q4.y;
        Qs[r][dq + 2] = q4.z; Qs[r][dq + 3] = q4.w;
        float4 k4 = *(const float4*)(kb + (size_t)(nBase + r) * DD + dq);
        Ks[r][dq + 0] = k4.x; Ks[r][dq + 1] = k4.y;
        Ks[r][dq + 2] = k4.z; Ks[r][dq + 3] = k4.w;
    }
    __syncthreads();

    float acc[4][4] = {};
    #pragma unroll 8
    for (int kk = 0; kk < 64; kk++) {
        float a[4], bvreg[4];
        #pragma unroll
        for (int i = 0; i < 4; i++) a[i] = Qs[ty * 4 + i][kk];
        #pragma unroll
        for (int j = 0; j < 4; j++) bvreg[j] = Ks[tx * 4 + j][kk];
        #pragma unroll
        for (int i = 0; i < 4; i++)
            #pragma unroll
            for (int j = 0; j < 4; j++)
                acc[i][j] = fmaf(a[i], bvreg[j], acc[i][j]);
    }

    const float inv_scale = 0.125f;   // 1/sqrt(64)
    float* wrow = wout + ((size_t)bh * SS + mBase) * SS + nBase;
    #pragma unroll
    for (int i = 0; i < 4; i++)
        #pragma unroll
        for (int j = 0; j < 4; j++)
            wrow[(size_t)(ty * 4 + i) * SS + tx * 4 + j] = acc[i][j] * inv_scale;
}

// ---------------------------------------------------------------------------
// Kernel 3: row softmax, in place on the weights region. One block per row,
// 256 threads x 4 elements.
// ---------------------------------------------------------------------------
__global__ void __launch_bounds__(256)
softmax_kernel(float* __restrict__ w)
{
    float* p = w + (size_t)blockIdx.x * SS;
    const int t = threadIdx.x;

    float v[4];
    float m = -INFINITY;
    #pragma unroll
    for (int i = 0; i < 4; i++) {
        v[i] = p[t + i * 256];
        m = fmaxf(m, v[i]);
    }

    __shared__ float red[16];

    // block max
    #pragma unroll
    for (int o = 16; o > 0; o >>= 1)
        m = fmaxf(m, __shfl_xor_sync(0xffffffffu, m, o));
    if ((t & 31) == 0) red[t >> 5] = m;
    __syncthreads();
    float bm = red[0];
    #pragma unroll
    for (int i = 1; i < 8; i++) bm = fmaxf(bm, red[i]);

    // exp + block sum
    float s = 0.f;
    #pragma unroll
    for (int i = 0; i < 4; i++) {
        v[i] = expf(v[i] - bm);
        s += v[i];
    }
    #pragma unroll
    for (int o = 16; o > 0; o >>= 1)
        s += __shfl_xor_sync(0xffffffffu, s, o);
    __syncthreads();                    // red[] reuse barrier
    if ((t & 31) == 0) red[8 + (t >> 5)] = s;
    __syncthreads();
    float bs = 0.f;
    #pragma unroll
    for (int i = 0; i < 8; i++) bs += red[8 + i];

    const float inv = 1.0f / bs;
    #pragma unroll
    for (int i = 0; i < 4; i++)
        p[t + i * 256] = v[i] * inv;
}

// ---------------------------------------------------------------------------
// Kernel 4: attn = W @ V per (b,h), written into the attn region of d_out in
// [B, S, D] layout. 64 (rows) x 64 (hd) tile, BK=32.
// ---------------------------------------------------------------------------
__global__ void __launch_bounds__(256)
attn_kernel(const float* __restrict__ w, float* __restrict__ out)
{
    const int bh = blockIdx.z;
    const int b = bh / HH, h = bh % HH;
    const int mBase = blockIdx.y * 64;

    const float* wb = w + (size_t)bh * SS * SS;
    const float* vb = g_v + (size_t)b * SS * DD + h * HD;

    __shared__ float Ws[64][33];   // [row][j-chunk]
    __shared__ float Vs[32][65];   // [j][d]

    const int tx = threadIdx.x % 16;
    const int ty = threadIdx.x / 16;

    float acc[4][4] = {};

    for (int j0 = 0; j0 < SS; j0 += 32) {
        // W tile: 64 rows x 32 cols, float4 (64*8 = 512 -> 2 iters)
        for (int i = threadIdx.x; i < 64 * 8; i += 256) {
            int r  = i / 8;
            int cq = (i % 8) * 4;
            float4 w4 = *(const float4*)(wb + (size_t)(mBase + r) * SS + j0 + cq);
            Ws[r][cq + 0] = w4.x; Ws[r][cq + 1] = w4.y;
            Ws[r][cq + 2] = w4.z; Ws[r][cq + 3] = w4.w;
        }
        // V tile: 32 rows x 64 cols, float4 (32*16 = 512 -> 2 iters)
        for (int i = threadIdx.x; i < 32 * 16; i += 256) {
            int r  = i / 16;
            int cq = (i % 16) * 4;
            float4 v4 = *(const float4*)(vb + (size_t)(j0 + r) * DD + cq);
            Vs[r][cq + 0] = v4.x; Vs[r][cq + 1] = v4.y;
            Vs[r][cq + 2] = v4.z; Vs[r][cq + 3] = v4.w;
        }
        __syncthreads();

        #pragma unroll 8
        for (int kk = 0; kk < 32; kk++) {
            float a[4], bvreg[4];
            #pragma unroll
            for (int i = 0; i < 4; i++) a[i] = Ws[ty * 4 + i][kk];
            #pragma unroll
            for (int j = 0; j < 4; j++) bvreg[j] = Vs[kk][tx * 4 + j];
            #pragma unroll
            for (int i = 0; i < 4; i++)
                #pragma unroll
                for (int j = 0; j < 4; j++)
                    acc[i][j] = fmaf(a[i], bvreg[j], acc[i][j]);
        }
        __syncthreads();
    }

    #pragma unroll
    for (int i = 0; i < 4; i++) {
        int m = mBase + ty * 4 + i;
        #pragma unroll
        for (int j = 0; j < 4; j++) {
            int d = tx * 4 + j;
            out[((size_t)b * SS + m) * DD + h * HD + d] = acc[i][j];
        }
    }
}

// ---------------------------------------------------------------------------
extern "C" void kernel_launch(void* const* d_in, const int* in_sizes, int n_in,
                              void* d_out, int out_size)
{
    const float* x  = (const float*)d_in[0];
    const float* Wq = (const float*)d_in[1];
    const float* bq = (const float*)d_in[2];
    const float* Wk = (const float*)d_in[3];
    const float* bk = (const float*)d_in[4];
    const float* Wv = (const float*)d_in[5];
    const float* bv = (const float*)d_in[6];

    float* out     = (float*)d_out;
    float* attn    = out;                                   // [B, S, D]
    float* weights = out + (size_t)BB * SS * DD;            // [B, H, S, S]

    dim3 gProj(DD / 64, MTOT / 64, 3);
    proj_kernel<<<gProj, 256>>>(x, Wq, bq, Wk, bk, Wv, bv);

    dim3 gSc(SS / 64, SS / 64, BB * HH);
    scores_kernel<<<gSc, 256>>>(weights);

    softmax_kernel<<<BB * HH * SS, 256>>>(weights);

    dim3 gAt(1, SS / 64, BB * HH);
    attn_kernel<<<gAt, 256>>>(weights, attn);
}

// round 7
// speedup vs baseline: 1.5648x; 1.5648x over previous
#include <cuda_runtime.h>
#include <math.h>

#define BB 8
#define SS 1024
#define DD 1024
#define HH 16
#define HD 64
#define MTOT (BB*SS)   // 8192

// scratch for q, k, v in [B*S, D] layout (head h lives in columns h*64..h*64+63)
__device__ float g_q[(size_t)MTOT * DD];
__device__ float g_k[(size_t)MTOT * DD];
__device__ float g_v[(size_t)MTOT * DD];

// ---------------------------------------------------------------------------
// Kernel 1: QKV projection. out = x @ W + b. 128x128 block tile, BK=16,
// 256 threads, 8x8 micro-tile, LDS.128 fetches from [k][row] smem layout.
// ---------------------------------------------------------------------------
__global__ void __launch_bounds__(256)
proj_kernel(const float* __restrict__ x,
            const float* __restrict__ Wq, const float* __restrict__ bq,
            const float* __restrict__ Wk, const float* __restrict__ bk,
            const float* __restrict__ Wv, const float* __restrict__ bv)
{
    const float* W; const float* bias; float* out;
    if (blockIdx.z == 0)      { W = Wq; bias = bq; out = g_q; }
    else if (blockIdx.z == 1) { W = Wk; bias = bk; out = g_k; }
    else                      { W = Wv; bias = bv; out = g_v; }

    __shared__ float As[16][132];   // [k][m], 132 keeps 16B row alignment
    __shared__ float Bs[16][132];   // [k][n]

    const int tid = threadIdx.x;
    const int tx = tid % 16;
    const int ty = tid / 16;
    const int mBase = blockIdx.y * 128;
    const int nBase = blockIdx.x * 128;

    float acc[8][8] = {};

    for (int k0 = 0; k0 < DD; k0 += 16) {
        // A tile: 128 rows x 16 k, transposed into [k][m]. 512 float4s, 2/thread.
        #pragma unroll
        for (int l = 0; l < 2; l++) {
            int idx = tid + l * 256;
            int m   = idx >> 2;            // 0..127
            int kq  = (idx & 3) * 4;       // 0,4,8,12
            float4 v4 = *(const float4*)(x + (size_t)(mBase + m) * DD + k0 + kq);
            As[kq + 0][m] = v4.x;
            As[kq + 1][m] = v4.y;
            As[kq + 2][m] = v4.z;
            As[kq + 3][m] = v4.w;
        }
        // B tile: 16 k x 128 n, direct float4 store. 512 float4s, 2/thread.
        #pragma unroll
        for (int l = 0; l < 2; l++) {
            int idx = tid + l * 256;
            int kk  = idx >> 5;            // 0..15
            int nq  = (idx & 31) * 4;      // 0..124
            float4 v4 = *(const float4*)(W + (size_t)(k0 + kk) * DD + nBase + nq);
            *(float4*)&Bs[kk][nq] = v4;
        }
        __syncthreads();

        #pragma unroll
        for (int kk = 0; kk < 16; kk++) {
            float4 a0 = *(const float4*)&As[kk][ty * 4];
            float4 a1 = *(const float4*)&As[kk][ty * 4 + 64];
            float4 b0 = *(const float4*)&Bs[kk][tx * 4];
            float4 b1 = *(const float4*)&Bs[kk][tx * 4 + 64];
            float a[8] = {a0.x, a0.y, a0.z, a0.w, a1.x, a1.y, a1.z, a1.w};
            float b[8] = {b0.x, b0.y, b0.z, b0.w, b1.x, b1.y, b1.z, b1.w};
            #pragma unroll
            for (int i = 0; i < 8; i++)
                #pragma unroll
                for (int j = 0; j < 8; j++)
                    acc[i][j] = fmaf(a[i], b[j], acc[i][j]);
        }
        __syncthreads();
    }

    float4 bia0 = *(const float4*)(bias + nBase + tx * 4);
    float4 bia1 = *(const float4*)(bias + nBase + tx * 4 + 64);
    #pragma unroll
    for (int i = 0; i < 8; i++) {
        int m = mBase + ty * 4 + (i < 4 ? i : 64 + i - 4);
        float4 o0, o1;
        o0.x = acc[i][0] + bia0.x; o0.y = acc[i][1] + bia0.y;
        o0.z = acc[i][2] + bia0.z; o0.w = acc[i][3] + bia0.w;
        o1.x = acc[i][4] + bia1.x; o1.y = acc[i][5] + bia1.y;
        o1.z = acc[i][6] + bia1.z; o1.w = acc[i][7] + bia1.w;
        *(float4*)(out + (size_t)m * DD + nBase + tx * 4)      = o0;
        *(float4*)(out + (size_t)m * DD + nBase + tx * 4 + 64) = o1;
    }
}

// ---------------------------------------------------------------------------
// Kernel 2: per-(b,h) scores = Q @ K^T / 8. 128x128 tile, K processed in two
// 32-chunks, 8x8 micro-tile.
// ---------------------------------------------------------------------------
__global__ void __launch_bounds__(256)
scores_kernel(float* __restrict__ wout)
{
    const int bh = blockIdx.z;          // 0..127
    const int b = bh / HH, h = bh % HH;
    const int mBase = blockIdx.y * 128;
    const int nBase = blockIdx.x * 128;

    const float* qb = g_q + (size_t)b * SS * DD + h * HD;
    const float* kb = g_k + (size_t)b * SS * DD + h * HD;

    __shared__ float Qs[32][132];   // [d][row]
    __shared__ float Ks[32][132];   // [d][row]

    const int tid = threadIdx.x;
    const int tx = tid % 16;
    const int ty = tid / 16;

    float acc[8][8] = {};

    for (int k0 = 0; k0 < HD; k0 += 32) {
        // 128 rows x 32 d each for Q and K, transposed. 1024 float4s, 4/thread.
        #pragma unroll
        for (int l = 0; l < 4; l++) {
            int idx = tid + l * 256;
            int r   = idx >> 3;            // 0..127
            int kq  = (idx & 7) * 4;       // 0..28
            float4 q4 = *(const float4*)(qb + (size_t)(mBase + r) * DD + k0 + kq);
            Qs[kq + 0][r] = q4.x; Qs[kq + 1][r] = q4.y;
            Qs[kq + 2][r] = q4.z; Qs[kq + 3][r] = q4.w;
            float4 k4 = *(const float4*)(kb + (size_t)(nBase + r) * DD + k0 + kq);
            Ks[kq + 0][r] = k4.x; Ks[kq + 1][r] = k4.y;
            Ks[kq + 2][r] = k4.z; Ks[kq + 3][r] = k4.w;
        }
        __syncthreads();

        #pragma unroll 8
        for (int kk = 0; kk < 32; kk++) {
            float4 a0 = *(const float4*)&Qs[kk][ty * 4];
            float4 a1 = *(const float4*)&Qs[kk][ty * 4 + 64];
            float4 b0 = *(const float4*)&Ks[kk][tx * 4];
            float4 b1 = *(const float4*)&Ks[kk][tx * 4 + 64];
            float a[8] = {a0.x, a0.y, a0.z, a0.w, a1.x, a1.y, a1.z, a1.w};
            float bb[8] = {b0.x, b0.y, b0.z, b0.w, b1.x, b1.y, b1.z, b1.w};
            #pragma unroll
            for (int i = 0; i < 8; i++)
                #pragma unroll
                for (int j = 0; j < 8; j++)
                    acc[i][j] = fmaf(a[i], bb[j], acc[i][j]);
        }
        __syncthreads();
    }

    const float inv_scale = 0.125f;   // 1/sqrt(64)
    float* wrow = wout + ((size_t)bh * SS + mBase) * SS + nBase;
    #pragma unroll
    for (int i = 0; i < 8; i++) {
        int r = ty * 4 + (i < 4 ? i : 64 + i - 4);
        float4 o0, o1;
        o0.x = acc[i][0] * inv_scale; o0.y = acc[i][1] * inv_scale;
        o0.z = acc[i][2] * inv_scale; o0.w = acc[i][3] * inv_scale;
        o1.x = acc[i][4] * inv_scale; o1.y = acc[i][5] * inv_scale;
        o1.z = acc[i][6] * inv_scale; o1.w = acc[i][7] * inv_scale;
        *(float4*)(wrow + (size_t)r * SS + tx * 4)      = o0;
        *(float4*)(wrow + (size_t)r * SS + tx * 4 + 64) = o1;
    }
}

// ---------------------------------------------------------------------------
// Kernel 3: row softmax, in place on the weights region.
// ---------------------------------------------------------------------------
__global__ void __launch_bounds__(256)
softmax_kernel(float* __restrict__ w)
{
    float* p = w + (size_t)blockIdx.x * SS;
    const int t = threadIdx.x;

    float v[4];
    float m = -INFINITY;
    #pragma unroll
    for (int i = 0; i < 4; i++) {
        v[i] = p[t + i * 256];
        m = fmaxf(m, v[i]);
    }

    __shared__ float red[16];

    #pragma unroll
    for (int o = 16; o > 0; o >>= 1)
        m = fmaxf(m, __shfl_xor_sync(0xffffffffu, m, o));
    if ((t & 31) == 0) red[t >> 5] = m;
    __syncthreads();
    float bm = red[0];
    #pragma unroll
    for (int i = 1; i < 8; i++) bm = fmaxf(bm, red[i]);

    float s = 0.f;
    #pragma unroll
    for (int i = 0; i < 4; i++) {
        v[i] = expf(v[i] - bm);
        s += v[i];
    }
    #pragma unroll
    for (int o = 16; o > 0; o >>= 1)
        s += __shfl_xor_sync(0xffffffffu, s, o);
    __syncthreads();
    if ((t & 31) == 0) red[8 + (t >> 5)] = s;
    __syncthreads();
    float bs = 0.f;
    #pragma unroll
    for (int i = 0; i < 8; i++) bs += red[8 + i];

    const float inv = 1.0f / bs;
    #pragma unroll
    for (int i = 0; i < 4; i++)
        p[t + i * 256] = v[i] * inv;
}

// ---------------------------------------------------------------------------
// Kernel 4: attn = W @ V per (b,h). 256 (rows) x 64 (hd) tile, BK=32,
// 256 threads, 8x8 micro-tile (rows split 4+4 at stride 128, cols at 32).
// ---------------------------------------------------------------------------
__global__ void __launch_bounds__(256)
attn_kernel(const float* __restrict__ w, float* __restrict__ out)
{
    const int bh = blockIdx.z;
    const int b = bh / HH, h = bh % HH;
    const int mBase = blockIdx.y * 256;

    const float* wb = w + (size_t)bh * SS * SS;
    const float* vb = g_v + (size_t)b * SS * DD + h * HD;

    __shared__ float Ws[32][264];   // [k][row], 33.8 KB
    __shared__ float Vs[32][68];    // [k][col],  8.7 KB

    const int tid = threadIdx.x;
    const int tx = tid % 8;          // cols
    const int ty = tid / 8;          // 0..31 row groups

    float acc[8][8] = {};

    for (int j0 = 0; j0 < SS; j0 += 32) {
        // W tile: 256 rows x 32 k, transposed. 2048 float4s, 8/thread.
        #pragma unroll
        for (int l = 0; l < 8; l++) {
            int idx = tid + l * 256;
            int r   = idx >> 3;            // 0..255
            int kq  = (idx & 7) * 4;       // 0..28
            float4 w4 = *(const float4*)(wb + (size_t)(mBase + r) * SS + j0 + kq);
            Ws[kq + 0][r] = w4.x; Ws[kq + 1][r] = w4.y;
            Ws[kq + 2][r] = w4.z; Ws[kq + 3][r] = w4.w;
        }
        // V tile: 32 k x 64 cols, direct float4. 512 float4s, 2/thread.
        #pragma unroll
        for (int l = 0; l < 2; l++) {
            int idx = tid + l * 256;
            int r   = idx >> 4;            // 0..31
            int cq  = (idx & 15) * 4;      // 0..60
            float4 v4 = *(const float4*)(vb + (size_t)(j0 + r) * DD + cq);
            *(float4*)&Vs[r][cq] = v4;
        }
        __syncthreads();

        #pragma unroll 8
        for (int kk = 0; kk < 32; kk++) {
            float4 a0 = *(const float4*)&Ws[kk][ty * 4];
            float4 a1 = *(const float4*)&Ws[kk][ty * 4 + 128];
            float4 b0 = *(const float4*)&Vs[kk][tx * 4];
            float4 b1 = *(const float4*)&Vs[kk][tx * 4 + 32];
            float a[8] = {a0.x, a0.y, a0.z, a0.w, a1.x, a1.y, a1.z, a1.w};
            float bb[8] = {b0.x, b0.y, b0.z, b0.w, b1.x, b1.y, b1.z, b1.w};
            #pragma unroll
            for (int i = 0; i < 8; i++)
                #pragma unroll
                for (int j = 0; j < 8; j++)
                    acc[i][j] = fmaf(a[i], bb[j], acc[i][j]);
        }
        __syncthreads();
    }

    #pragma unroll
    for (int i = 0; i < 8; i++) {
        int m = mBase + ty * 4 + (i < 4 ? i : 128 + i - 4);
        float4 o0, o1;
        o0.x = acc[i][0]; o0.y = acc[i][1]; o0.z = acc[i][2]; o0.w = acc[i][3];
        o1.x = acc[i][4]; o1.y = acc[i][5]; o1.z = acc[i][6]; o1.w = acc[i][7];
        float* orow = out + ((size_t)b * SS + m) * DD + h * HD;
        *(float4*)(orow + tx * 4)      = o0;
        *(float4*)(orow + tx * 4 + 32) = o1;
    }
}

// ---------------------------------------------------------------------------
extern "C" void kernel_launch(void* const* d_in, const int* in_sizes, int n_in,
                              void* d_out, int out_size)
{
    const float* x  = (const float*)d_in[0];
    const float* Wq = (const float*)d_in[1];
    const float* bq = (const float*)d_in[2];
    const float* Wk = (const float*)d_in[3];
    const float* bk = (const float*)d_in[4];
    const float* Wv = (const float*)d_in[5];
    const float* bv = (const float*)d_in[6];

    float* out     = (float*)d_out;
    float* attn    = out;                                   // [B, S, D]
    float* weights = out + (size_t)BB * SS * DD;            // [B, H, S, S]

    dim3 gProj(DD / 128, MTOT / 128, 3);
    proj_kernel<<<gProj, 256>>>(x, Wq, bq, Wk, bk, Wv, bv);

    dim3 gSc(SS / 128, SS / 128, BB * HH);
    scores_kernel<<<gSc, 256>>>(weights);

    softmax_kernel<<<BB * HH * SS, 256>>>(weights);

    dim3 gAt(1, SS / 256, BB * HH);
    attn_kernel<<<gAt, 256>>>(weights, attn);
}

// round 8
// speedup vs baseline: 2.8074x; 1.7941x over previous
#include <cuda_runtime.h>
#include <cuda_bf16.h>
#include <math.h>
#include <stdint.h>

#define BB 8
#define SS 1024
#define DD 1024
#define HH 16
#define HD 64
#define MTOT (BB*SS)   // 8192

// q/k/v stored as split bf16 (value = hi + lo), layout [B*S][D]
__device__ __nv_bfloat16 g_qh[(size_t)MTOT * DD];
__device__ __nv_bfloat16 g_ql[(size_t)MTOT * DD];
__device__ __nv_bfloat16 g_kh[(size_t)MTOT * DD];
__device__ __nv_bfloat16 g_kl[(size_t)MTOT * DD];
__device__ __nv_bfloat16 g_vh[(size_t)MTOT * DD];
__device__ __nv_bfloat16 g_vl[(size_t)MTOT * DD];

// ---------------------------------------------------------------------------
// helpers
// ---------------------------------------------------------------------------
__device__ __forceinline__ uint32_t s2u(const void* p) {
    return (uint32_t)__cvta_generic_to_shared(p);
}
__device__ __forceinline__ void ldm_x4(uint32_t* r, uint32_t a) {
    asm volatile("ldmatrix.sync.aligned.m8n8.x4.shared.b16 {%0,%1,%2,%3}, [%4];\n"
        : "=r"(r[0]), "=r"(r[1]), "=r"(r[2]), "=r"(r[3]) : "r"(a));
}
__device__ __forceinline__ void ldm_x4t(uint32_t* r, uint32_t a) {
    asm volatile("ldmatrix.sync.aligned.m8n8.x4.trans.shared.b16 {%0,%1,%2,%3}, [%4];\n"
        : "=r"(r[0]), "=r"(r[1]), "=r"(r[2]), "=r"(r[3]) : "r"(a));
}
__device__ __forceinline__ void mma16816(float* c, const uint32_t* a, uint32_t b0, uint32_t b1) {
    asm volatile("mma.sync.aligned.m16n8k16.row.col.f32.bf16.bf16.f32 "
        "{%0,%1,%2,%3}, {%4,%5,%6,%7}, {%8,%9}, {%0,%1,%2,%3};\n"
        : "+f"(c[0]), "+f"(c[1]), "+f"(c[2]), "+f"(c[3])
        : "r"(a[0]), "r"(a[1]), "r"(a[2]), "r"(a[3]), "r"(b0), "r"(b1));
}
__device__ __forceinline__ void splitf(float f, __nv_bfloat16& h, __nv_bfloat16& l) {
    h = __float2bfloat16(f);
    l = __float2bfloat16(f - __bfloat162float(h));
}
// split a float4 into 4 hi + 4 lo bf16, stored contiguously (8B each)
__device__ __forceinline__ void split4s(float4 v, __nv_bfloat16* ph, __nv_bfloat16* pl) {
    __nv_bfloat16 h0, l0, h1, l1, h2, l2, h3, l3;
    splitf(v.x, h0, l0); splitf(v.y, h1, l1);
    splitf(v.z, h2, l2); splitf(v.w, h3, l3);
    *(__nv_bfloat162*)(ph + 0) = __halves2bfloat162(h0, h1);
    *(__nv_bfloat162*)(ph + 2) = __halves2bfloat162(h2, h3);
    *(__nv_bfloat162*)(pl + 0) = __halves2bfloat162(l0, l1);
    *(__nv_bfloat162*)(pl + 2) = __halves2bfloat162(l2, l3);
}

// ---------------------------------------------------------------------------
// Kernel 1: QKV projection, split-bf16 tensor-core GEMM.
// Block tile 128x128, BK=32, 8 warps (2m x 4n), warp tile 64x32.
// A = x [m][k] (convert inline), B = W [k][n] (convert inline, ldmatrix.trans).
// Output written as split bf16 into g_{q,k,v}{h,l}.
// ---------------------------------------------------------------------------
#define PLDA 40     // A row stride (elems): 80B, conflict-free + 16B aligned
#define PLDB 136    // B row stride (elems): 272B

__global__ void __launch_bounds__(256)
proj_kernel(const float* __restrict__ x,
            const float* __restrict__ Wq, const float* __restrict__ bq,
            const float* __restrict__ Wk, const float* __restrict__ bk,
            const float* __restrict__ Wv, const float* __restrict__ bv)
{
    const float* W; const float* bias;
    __nv_bfloat16* outh; __nv_bfloat16* outl;
    if (blockIdx.z == 0)      { W = Wq; bias = bq; outh = g_qh; outl = g_ql; }
    else if (blockIdx.z == 1) { W = Wk; bias = bk; outh = g_kh; outl = g_kl; }
    else                      { W = Wv; bias = bv; outh = g_vh; outl = g_vl; }

    __shared__ __align__(16) __nv_bfloat16 Ah[128 * PLDA];
    __shared__ __align__(16) __nv_bfloat16 Al[128 * PLDA];
    __shared__ __align__(16) __nv_bfloat16 Bh[32 * PLDB];
    __shared__ __align__(16) __nv_bfloat16 Bl[32 * PLDB];

    const int tid  = threadIdx.x;
    const int lane = tid & 31;
    const int wid  = tid >> 5;
    const int wm   = wid >> 2;          // 0..1
    const int wn   = wid & 3;           // 0..3
    const int mBase = blockIdx.y * 128;
    const int nBase = blockIdx.x * 128;

    // ldmatrix addressing lanes
    const int arow = lane & 15;                      // A: row within m16
    const int ak8  = (lane >> 4) * 8;                // A: k 8-offset
    const int trow = (lane & 7) + 8 * ((lane >> 3) & 1);  // trans: source k row
    const int tn8  = 8 * (lane >> 4);                // trans: n 8-offset

    float acc[4][4][4] = {};

    for (int k0 = 0; k0 < DD; k0 += 32) {
        // A tile: 128x32 f32 -> split bf16, [m][k]
        #pragma unroll
        for (int l = 0; l < 4; l++) {
            int idx = tid + l * 256;
            int m = idx >> 3, kq = (idx & 7) * 4;
            float4 v = *(const float4*)(x + (size_t)(mBase + m) * DD + k0 + kq);
            split4s(v, &Ah[m * PLDA + kq], &Al[m * PLDA + kq]);
        }
        // B tile: 32x128 f32 -> split bf16, [k][n]
        #pragma unroll
        for (int l = 0; l < 4; l++) {
            int idx = tid + l * 256;
            int kk = idx >> 5, nq = (idx & 31) * 4;
            float4 v = *(const float4*)(W + (size_t)(k0 + kk) * DD + nBase + nq);
            split4s(v, &Bh[kk * PLDB + nq], &Bl[kk * PLDB + nq]);
        }
        __syncthreads();

        #pragma unroll
        for (int kk = 0; kk < 32; kk += 16) {
            uint32_t ah[4][4], al[4][4], bh[2][4], bl[2][4];
            #pragma unroll
            for (int mt = 0; mt < 4; mt++) {
                int ro = (wm * 64 + mt * 16 + arow) * PLDA + kk + ak8;
                ldm_x4(ah[mt], s2u(&Ah[ro]));
                ldm_x4(al[mt], s2u(&Al[ro]));
            }
            #pragma unroll
            for (int g = 0; g < 2; g++) {
                int ro = (kk + trow) * PLDB + wn * 32 + g * 16 + tn8;
                ldm_x4t(bh[g], s2u(&Bh[ro]));
                ldm_x4t(bl[g], s2u(&Bl[ro]));
            }
            #pragma unroll
            for (int mt = 0; mt < 4; mt++)
                #pragma unroll
                for (int g = 0; g < 2; g++)
                    #pragma unroll
                    for (int h2 = 0; h2 < 2; h2++) {
                        float* c = acc[mt][g * 2 + h2];
                        mma16816(c, ah[mt], bh[g][h2 * 2], bh[g][h2 * 2 + 1]);
                        mma16816(c, ah[mt], bl[g][h2 * 2], bl[g][h2 * 2 + 1]);
                        mma16816(c, al[mt], bh[g][h2 * 2], bh[g][h2 * 2 + 1]);
                    }
        }
        __syncthreads();
    }

    // epilogue: add bias, split, store
    const int tq = lane >> 2, tr = lane & 3;
    #pragma unroll
    for (int mt = 0; mt < 4; mt++)
        #pragma unroll
        for (int nidx = 0; nidx < 4; nidx++) {
            int ncol = nBase + wn * 32 + nidx * 8 + tr * 2;
            float2 bia = *(const float2*)(bias + ncol);
            #pragma unroll
            for (int rh = 0; rh < 2; rh++) {
                int row = mBase + wm * 64 + mt * 16 + tq + rh * 8;
                float v0 = acc[mt][nidx][rh * 2 + 0] + bia.x;
                float v1 = acc[mt][nidx][rh * 2 + 1] + bia.y;
                __nv_bfloat16 h0, l0, h1, l1;
                splitf(v0, h0, l0); splitf(v1, h1, l1);
                size_t off = (size_t)row * DD + ncol;
                *(__nv_bfloat162*)(outh + off) = __halves2bfloat162(h0, h1);
                *(__nv_bfloat162*)(outl + off) = __halves2bfloat162(l0, l1);
            }
        }
}

// ---------------------------------------------------------------------------
// Kernel 2: scores = Q @ K^T / 8 per (b,h). Block 128x128, BK=32 (K-dim 64).
// A = Q [m][d] split bf16, B = K [n][d] split bf16 (ldmatrix no-trans).
// ---------------------------------------------------------------------------
__global__ void __launch_bounds__(256)
scores_kernel(float* __restrict__ wout)
{
    const int bh = blockIdx.z;
    const int b = bh / HH, h = bh % HH;
    const int mBase = blockIdx.y * 128;
    const int nBase = blockIdx.x * 128;

    const __nv_bfloat16* qh = g_qh + (size_t)b * SS * DD + h * HD;
    const __nv_bfloat16* ql = g_ql + (size_t)b * SS * DD + h * HD;
    const __nv_bfloat16* kh = g_kh + (size_t)b * SS * DD + h * HD;
    const __nv_bfloat16* kl = g_kl + (size_t)b * SS * DD + h * HD;

    __shared__ __align__(16) __nv_bfloat16 Qh[128 * PLDA];
    __shared__ __align__(16) __nv_bfloat16 Ql[128 * PLDA];
    __shared__ __align__(16) __nv_bfloat16 Kh[128 * PLDA];
    __shared__ __align__(16) __nv_bfloat16 Kl[128 * PLDA];

    const int tid  = threadIdx.x;
    const int lane = tid & 31;
    const int wid  = tid >> 5;
    const int wm   = wid >> 2;          // 0..1
    const int wn   = wid & 3;           // 0..3

    const int arow = lane & 15;
    const int ak8  = (lane >> 4) * 8;
    const int nrow = (lane & 7) + 8 * (lane >> 4);        // B no-trans: n row
    const int bk8  = 8 * ((lane >> 3) & 1);               // B no-trans: k offset

    float acc[4][4][4] = {};

    for (int k0 = 0; k0 < HD; k0 += 32) {
        // copy 4 tiles of 128x32 bf16, uint4 (8 elems) per access
        #pragma unroll
        for (int l = 0; l < 2; l++) {
            int idx = tid + l * 256;        // 0..511
            int r = idx >> 2, cq = (idx & 3) * 8;
            *(uint4*)&Qh[r * PLDA + cq] = *(const uint4*)(qh + (size_t)(mBase + r) * DD + k0 + cq);
            *(uint4*)&Ql[r * PLDA + cq] = *(const uint4*)(ql + (size_t)(mBase + r) * DD + k0 + cq);
            *(uint4*)&Kh[r * PLDA + cq] = *(const uint4*)(kh + (size_t)(nBase + r) * DD + k0 + cq);
            *(uint4*)&Kl[r * PLDA + cq] = *(const uint4*)(kl + (size_t)(nBase + r) * DD + k0 + cq);
        }
        __syncthreads();

        #pragma unroll
        for (int kk = 0; kk < 32; kk += 16) {
            uint32_t ah[4][4], al[4][4], bh[2][4], bl[2][4];
            #pragma unroll
            for (int mt = 0; mt < 4; mt++) {
                int ro = (wm * 64 + mt * 16 + arow) * PLDA + kk + ak8;
                ldm_x4(ah[mt], s2u(&Qh[ro]));
                ldm_x4(al[mt], s2u(&Ql[ro]));
            }
            #pragma unroll
            for (int g = 0; g < 2; g++) {
                int ro = (wn * 32 + g * 16 + nrow) * PLDA + kk + bk8;
                ldm_x4(bh[g], s2u(&Kh[ro]));
                ldm_x4(bl[g], s2u(&Kl[ro]));
            }
            #pragma unroll
            for (int mt = 0; mt < 4; mt++)
                #pragma unroll
                for (int g = 0; g < 2; g++)
                    #pragma unroll
                    for (int h2 = 0; h2 < 2; h2++) {
                        float* c = acc[mt][g * 2 + h2];
                        mma16816(c, ah[mt], bh[g][h2 * 2], bh[g][h2 * 2 + 1]);
                        mma16816(c, ah[mt], bl[g][h2 * 2], bl[g][h2 * 2 + 1]);
                        mma16816(c, al[mt], bh[g][h2 * 2], bh[g][h2 * 2 + 1]);
                    }
        }
        __syncthreads();
    }

    const float inv_scale = 0.125f;     // 1/sqrt(64)
    const int tq = lane >> 2, tr = lane & 3;
    #pragma unroll
    for (int mt = 0; mt < 4; mt++)
        #pragma unroll
        for (int nidx = 0; nidx < 4; nidx++) {
            int ncol = nBase + wn * 32 + nidx * 8 + tr * 2;
            #pragma unroll
            for (int rh = 0; rh < 2; rh++) {
                int row = mBase + wm * 64 + mt * 16 + tq + rh * 8;
                float2 o;
                o.x = acc[mt][nidx][rh * 2 + 0] * inv_scale;
                o.y = acc[mt][nidx][rh * 2 + 1] * inv_scale;
                *(float2*)(wout + ((size_t)bh * SS + row) * SS + ncol) = o;
            }
        }
}

// ---------------------------------------------------------------------------
// Kernel 3: row softmax, in place on the weights region.
// ---------------------------------------------------------------------------
__global__ void __launch_bounds__(256)
softmax_kernel(float* __restrict__ w)
{
    float* p = w + (size_t)blockIdx.x * SS;
    const int t = threadIdx.x;

    float v[4];
    float m = -INFINITY;
    #pragma unroll
    for (int i = 0; i < 4; i++) {
        v[i] = p[t + i * 256];
        m = fmaxf(m, v[i]);
    }

    __shared__ float red[16];

    #pragma unroll
    for (int o = 16; o > 0; o >>= 1)
        m = fmaxf(m, __shfl_xor_sync(0xffffffffu, m, o));
    if ((t & 31) == 0) red[t >> 5] = m;
    __syncthreads();
    float bm = red[0];
    #pragma unroll
    for (int i = 1; i < 8; i++) bm = fmaxf(bm, red[i]);

    float s = 0.f;
    #pragma unroll
    for (int i = 0; i < 4; i++) {
        v[i] = expf(v[i] - bm);
        s += v[i];
    }
    #pragma unroll
    for (int o = 16; o > 0; o >>= 1)
        s += __shfl_xor_sync(0xffffffffu, s, o);
    __syncthreads();
    if ((t & 31) == 0) red[8 + (t >> 5)] = s;
    __syncthreads();
    float bs = 0.f;
    #pragma unroll
    for (int i = 0; i < 8; i++) bs += red[8 + i];

    const float inv = 1.0f / bs;
    #pragma unroll
    for (int i = 0; i < 4; i++)
        p[t + i * 256] = v[i] * inv;
}

// ---------------------------------------------------------------------------
// Kernel 4: attn = P @ V per (b,h). Block 128(m) x 64(n=hd), BK=32.
// A = softmaxed weights f32 (convert inline), B = V [k][n] split bf16 (trans).
// 8 warps (4m x 2n), warp tile 32x32.
// ---------------------------------------------------------------------------
#define VLDB 72     // V row stride (elems): 144B

__global__ void __launch_bounds__(256)
attn_kernel(const float* __restrict__ w, float* __restrict__ out)
{
    const int bh = blockIdx.z;
    const int b = bh / HH, h = bh % HH;
    const int mBase = blockIdx.y * 128;

    const float* wb = w + (size_t)bh * SS * SS;
    const __nv_bfloat16* vh = g_vh + (size_t)b * SS * DD + h * HD;
    const __nv_bfloat16* vl = g_vl + (size_t)b * SS * DD + h * HD;

    __shared__ __align__(16) __nv_bfloat16 Ahs[128 * PLDA];
    __shared__ __align__(16) __nv_bfloat16 Als[128 * PLDA];
    __shared__ __align__(16) __nv_bfloat16 Vh[32 * VLDB];
    __shared__ __align__(16) __nv_bfloat16 Vl[32 * VLDB];

    const int tid  = threadIdx.x;
    const int lane = tid & 31;
    const int wid  = tid >> 5;
    const int wm   = wid >> 1;          // 0..3
    const int wn   = wid & 1;           // 0..1

    const int arow = lane & 15;
    const int ak8  = (lane >> 4) * 8;
    const int trow = (lane & 7) + 8 * ((lane >> 3) & 1);
    const int tn8  = 8 * (lane >> 4);

    float acc[2][4][4] = {};

    for (int j0 = 0; j0 < SS; j0 += 32) {
        // A (weights) tile: 128x32 f32 -> split bf16
        #pragma unroll
        for (int l = 0; l < 4; l++) {
            int idx = tid + l * 256;
            int r = idx >> 3, kq = (idx & 7) * 4;
            float4 v = *(const float4*)(wb + (size_t)(mBase + r) * SS + j0 + kq);
            split4s(v, &Ahs[r * PLDA + kq], &Als[r * PLDA + kq]);
        }
        // V tile: 32x64 split bf16, straight copy
        {
            int r = tid >> 3, cq = (tid & 7) * 8;
            *(uint4*)&Vh[r * VLDB + cq] = *(const uint4*)(vh + (size_t)(j0 + r) * DD + cq);
            *(uint4*)&Vl[r * VLDB + cq] = *(const uint4*)(vl + (size_t)(j0 + r) * DD + cq);
        }
        __syncthreads();

        #pragma unroll
        for (int kk = 0; kk < 32; kk += 16) {
            uint32_t ah[2][4], al[2][4], bh[2][4], bl[2][4];
            #pragma unroll
            for (int mt = 0; mt < 2; mt++) {
                int ro = (wm * 32 + mt * 16 + arow) * PLDA + kk + ak8;
                ldm_x4(ah[mt], s2u(&Ahs[ro]));
                ldm_x4(al[mt], s2u(&Als[ro]));
            }
            #pragma unroll
            for (int g = 0; g < 2; g++) {
                int ro = (kk + trow) * VLDB + wn * 32 + g * 16 + tn8;
                ldm_x4t(bh[g], s2u(&Vh[ro]));
                ldm_x4t(bl[g], s2u(&Vl[ro]));
            }
            #pragma unroll
            for (int mt = 0; mt < 2; mt++)
                #pragma unroll
                for (int g = 0; g < 2; g++)
                    #pragma unroll
                    for (int h2 = 0; h2 < 2; h2++) {
                        float* c = acc[mt][g * 2 + h2];
                        mma16816(c, ah[mt], bh[g][h2 * 2], bh[g][h2 * 2 + 1]);
                        mma16816(c, ah[mt], bl[g][h2 * 2], bl[g][h2 * 2 + 1]);
                        mma16816(c, al[mt], bh[g][h2 * 2], bh[g][h2 * 2 + 1]);
                    }
        }
        __syncthreads();
    }

    const int tq = lane >> 2, tr = lane & 3;
    #pragma unroll
    for (int mt = 0; mt < 2; mt++)
        #pragma unroll
        for (int nidx = 0; nidx < 4; nidx++) {
            int ncol = wn * 32 + nidx * 8 + tr * 2;
            #pragma unroll
            for (int rh = 0; rh < 2; rh++) {
                int row = mBase + wm * 32 + mt * 16 + tq + rh * 8;
                float2 o;
                o.x = acc[mt][nidx][rh * 2 + 0];
                o.y = acc[mt][nidx][rh * 2 + 1];
                *(float2*)(out + ((size_t)b * SS + row) * DD + h * HD + ncol) = o;
            }
        }
}

// ---------------------------------------------------------------------------
extern "C" void kernel_launch(void* const* d_in, const int* in_sizes, int n_in,
                              void* d_out, int out_size)
{
    const float* x  = (const float*)d_in[0];
    const float* Wq = (const float*)d_in[1];
    const float* bq = (const float*)d_in[2];
    const float* Wk = (const float*)d_in[3];
    const float* bk = (const float*)d_in[4];
    const float* Wv = (const float*)d_in[5];
    const float* bv = (const float*)d_in[6];

    float* out     = (float*)d_out;
    float* attn    = out;                                   // [B, S, D]
    float* weights = out + (size_t)BB * SS * DD;            // [B, H, S, S]

    dim3 gProj(DD / 128, MTOT / 128, 3);
    proj_kernel<<<gProj, 256>>>(x, Wq, bq, Wk, bk, Wv, bv);

    dim3 gSc(SS / 128, SS / 128, BB * HH);
    scores_kernel<<<gSc, 256>>>(weights);

    softmax_kernel<<<BB * HH * SS, 256>>>(weights);

    dim3 gAt(1, SS / 128, BB * HH);
    attn_kernel<<<gAt, 256>>>(weights, attn);
}